// round 8
// baseline (speedup 1.0000x reference)
#include <cuda_runtime.h>
#include <cuda_bf16.h>
#include <cstdint>
#include <cstddef>

#define DEVI __device__ __forceinline__

// ---------------- scratch (device globals; no allocation) ----------------
__device__ float g_V[8192 * 64];                 // stage-1 output
__device__ float g_H[(size_t)8192 * 4096];       // stage-2 output (128 MB)

// ---------------- helpers ----------------
DEVI float to_tf32(float x) {
    uint32_t u;
    asm("cvt.rna.tf32.f32 %0, %1;" : "=r"(u) : "f"(x));
    return __uint_as_float(u);
}

DEVI void mma8(float c[4], const uint32_t a[4], const uint32_t b[2]) {
    asm("mma.sync.aligned.m16n8k8.row.col.f32.tf32.tf32.f32 "
        "{%0,%1,%2,%3}, {%4,%5,%6,%7}, {%8,%9}, {%0,%1,%2,%3};\n"
        : "+f"(c[0]), "+f"(c[1]), "+f"(c[2]), "+f"(c[3])
        : "r"(a[0]), "r"(a[1]), "r"(a[2]), "r"(a[3]),
          "r"(b[0]), "r"(b[1]));
}

// ---------------- GEMM: C[M,N] = epi( A[M,K] @ B[N,K]^T + bias [+ resid] ) ----
// EPI: 0 = +bias ; 1 = +bias +resid ; 2 = +bias, relu
// Requirements: M % BM == 0, N % BN == 0, K % 32 == 0. 256 threads.
template <int BM, int BN, int EPI>
__global__ void __launch_bounds__(256, 1)
gemm_tf32_kernel(const float* __restrict__ A,
                 const float* __restrict__ B,
                 const float* __restrict__ bias,
                 const float* __restrict__ resid,
                 float* __restrict__ C,
                 int M, int N, int K)
{
    constexpr int MT = BM / 32;   // warp m-tiles (16 rows each) AND gmem-load iters
    constexpr int NT = BN / 32;   // warp n-tiles (8 cols each)  AND gmem-load iters
    constexpr int LD = 36;        // padded smem row stride (floats)

    extern __shared__ float smem[];
    float* const As0 = smem;
    float* const As1 = smem + BM * LD;
    float* const Bs0 = smem + 2 * BM * LD;
    float* const Bs1 = smem + 2 * BM * LD + BN * LD;
    float* const Asb[2] = { As0, As1 };
    float* const Bsb[2] = { Bs0, Bs1 };

    const int tid  = threadIdx.x;
    const int lane = tid & 31;
    const int wid  = tid >> 5;
    const int g    = lane >> 2;   // groupID (0..7)
    const int tig  = lane & 3;    // thread-in-group (0..3)

    const int wm = (wid >> 2) * (BM / 2);   // warp m offset (2 warp-rows)
    const int wn = (wid & 3) * (BN / 4);    // warp n offset (4 warp-cols)

    const float* Ab = A + (size_t)blockIdx.y * BM * K;
    const float* Bb = B + (size_t)blockIdx.x * BN * K;

    // gmem loader coords: 32 rows per pass, 8 threads x float4 per row
    const int lr = tid >> 3;          // 0..31
    const int lc = (tid & 7) * 4;     // 0,4,...,28

    float4 ra[MT], rb[NT];
    float acc[MT][NT][4];
#pragma unroll
    for (int mt = 0; mt < MT; ++mt)
#pragma unroll
        for (int nt = 0; nt < NT; ++nt)
#pragma unroll
            for (int i = 0; i < 4; ++i) acc[mt][nt][i] = 0.f;

    const int ktiles = K >> 5;

    // ---- prologue: load tile 0, round to tf32, store to buffer 0 ----
#pragma unroll
    for (int i = 0; i < MT; ++i)
        ra[i] = *(const float4*)(Ab + (size_t)(lr + 32 * i) * K + lc);
#pragma unroll
    for (int i = 0; i < NT; ++i)
        rb[i] = *(const float4*)(Bb + (size_t)(lr + 32 * i) * K + lc);
#pragma unroll
    for (int i = 0; i < MT; ++i) {
        float4 t = ra[i];
        t.x = to_tf32(t.x); t.y = to_tf32(t.y); t.z = to_tf32(t.z); t.w = to_tf32(t.w);
        *(float4*)&As0[(lr + 32 * i) * LD + lc] = t;
    }
#pragma unroll
    for (int i = 0; i < NT; ++i) {
        float4 t = rb[i];
        t.x = to_tf32(t.x); t.y = to_tf32(t.y); t.z = to_tf32(t.z); t.w = to_tf32(t.w);
        *(float4*)&Bs0[(lr + 32 * i) * LD + lc] = t;
    }
    __syncthreads();

    // ---- main loop ----
    for (int kt = 0; kt < ktiles; ++kt) {
        const int cur = kt & 1;
        const bool more = (kt + 1) < ktiles;

        if (more) {
            const int ko = (kt + 1) * 32;
#pragma unroll
            for (int i = 0; i < MT; ++i)
                ra[i] = *(const float4*)(Ab + (size_t)(lr + 32 * i) * K + ko + lc);
#pragma unroll
            for (int i = 0; i < NT; ++i)
                rb[i] = *(const float4*)(Bb + (size_t)(lr + 32 * i) * K + ko + lc);
        }

        const float* __restrict__ Ac = Asb[cur];
        const float* __restrict__ Bc = Bsb[cur];
#pragma unroll
        for (int ks = 0; ks < 4; ++ks) {
            uint32_t af[MT][4];
            uint32_t bf[NT][2];
            const int c0 = ks * 8 + tig;
#pragma unroll
            for (int mt = 0; mt < MT; ++mt) {
                const int r0 = wm + mt * 16 + g;
                af[mt][0] = __float_as_uint(Ac[r0 * LD + c0]);
                af[mt][1] = __float_as_uint(Ac[(r0 + 8) * LD + c0]);
                af[mt][2] = __float_as_uint(Ac[r0 * LD + c0 + 4]);
                af[mt][3] = __float_as_uint(Ac[(r0 + 8) * LD + c0 + 4]);
            }
#pragma unroll
            for (int nt = 0; nt < NT; ++nt) {
                const int r0 = wn + nt * 8 + g;
                bf[nt][0] = __float_as_uint(Bc[r0 * LD + c0]);
                bf[nt][1] = __float_as_uint(Bc[r0 * LD + c0 + 4]);
            }
#pragma unroll
            for (int mt = 0; mt < MT; ++mt)
#pragma unroll
                for (int nt = 0; nt < NT; ++nt)
                    mma8(acc[mt][nt], af[mt], bf[nt]);
        }

        if (more) {
            float* const An = Asb[cur ^ 1];
            float* const Bn = Bsb[cur ^ 1];
#pragma unroll
            for (int i = 0; i < MT; ++i) {
                float4 t = ra[i];
                t.x = to_tf32(t.x); t.y = to_tf32(t.y); t.z = to_tf32(t.z); t.w = to_tf32(t.w);
                *(float4*)&An[(lr + 32 * i) * LD + lc] = t;
            }
#pragma unroll
            for (int i = 0; i < NT; ++i) {
                float4 t = rb[i];
                t.x = to_tf32(t.x); t.y = to_tf32(t.y); t.z = to_tf32(t.z); t.w = to_tf32(t.w);
                *(float4*)&Bn[(lr + 32 * i) * LD + lc] = t;
            }
        }
        __syncthreads();
    }

    // ---- epilogue ----
    const int m0 = blockIdx.y * BM + wm;
    const int n0 = blockIdx.x * BN + wn;
#pragma unroll
    for (int mt = 0; mt < MT; ++mt) {
#pragma unroll
        for (int nt = 0; nt < NT; ++nt) {
            const int m = m0 + mt * 16 + g;
            const int n = n0 + nt * 8 + 2 * tig;
            const float2 bb = *(const float2*)(bias + n);
            float v0 = acc[mt][nt][0] + bb.x;
            float v1 = acc[mt][nt][1] + bb.y;
            float v2 = acc[mt][nt][2] + bb.x;
            float v3 = acc[mt][nt][3] + bb.y;
            if (EPI == 1) {
                const float2 r0 = *(const float2*)(resid + (size_t)m * N + n);
                const float2 r1 = *(const float2*)(resid + (size_t)(m + 8) * N + n);
                v0 += r0.x; v1 += r0.y; v2 += r1.x; v3 += r1.y;
            }
            if (EPI == 2) {
                v0 = fmaxf(v0, 0.f); v1 = fmaxf(v1, 0.f);
                v2 = fmaxf(v2, 0.f); v3 = fmaxf(v3, 0.f);
            }
            *(float2*)(C + (size_t)m * N + n)       = make_float2(v0, v1);
            *(float2*)(C + (size_t)(m + 8) * N + n) = make_float2(v2, v3);
        }
    }
}

// ---------------- launch ----------------
// Inputs (metadata order): x, Wq, bq, Wk, bk, Wv, bv, Wo, bo, Wn, bn
// softmax over a singleton axis => attn weights are all 1 => attended == v.
// q, k, Wq, bq, Wk, bk are dead code.
extern "C" void kernel_launch(void* const* d_in, const int* in_sizes, int n_in,
                              void* d_out, int out_size)
{
    const float* x  = (const float*)d_in[0];
    const float* Wv = (const float*)d_in[5];
    const float* bv = (const float*)d_in[6];
    const float* Wo = (const float*)d_in[7];
    const float* bo = (const float*)d_in[8];
    const float* Wn = (const float*)d_in[9];
    const float* bn = (const float*)d_in[10];
    float* out = (float*)d_out;

    float *V = nullptr, *H = nullptr;
    cudaGetSymbolAddress((void**)&V, g_V);
    cudaGetSymbolAddress((void**)&H, g_H);

    constexpr int SM64  = 2 * (64 + 64)   * 36 * (int)sizeof(float);  // 36864
    constexpr int SM128 = 2 * (128 + 128) * 36 * (int)sizeof(float);  // 73728

    cudaFuncSetAttribute(gemm_tf32_kernel<64, 64, 0>,
                         cudaFuncAttributeMaxDynamicSharedMemorySize, SM64);
    cudaFuncSetAttribute(gemm_tf32_kernel<128, 128, 1>,
                         cudaFuncAttributeMaxDynamicSharedMemorySize, SM128);
    cudaFuncSetAttribute(gemm_tf32_kernel<128, 128, 2>,
                         cudaFuncAttributeMaxDynamicSharedMemorySize, SM128);

    // Stage 1: V[8192,64] = x @ Wv^T + bv         (M=8192, N=64,   K=4096)
    gemm_tf32_kernel<64, 64, 0><<<dim3(1, 128), 256, SM64>>>(
        x, Wv, bv, nullptr, V, 8192, 64, 4096);

    // Stage 2: H[8192,4096] = V @ Wo^T + bo + x   (M=8192, N=4096, K=64)
    gemm_tf32_kernel<128, 128, 1><<<dim3(32, 64), 256, SM128>>>(
        V, Wo, bo, x, H, 8192, 4096, 64);

    // Stage 3: out = relu(H @ Wn^T + bn)          (M=8192, N=4096, K=4096)
    gemm_tf32_kernel<128, 128, 2><<<dim3(32, 64), 256, SM128>>>(
        H, Wn, bn, nullptr, out, 8192, 4096, 4096);
}

// round 12
// speedup vs baseline: 1.6410x; 1.6410x over previous
#include <cuda_runtime.h>
#include <cuda_bf16.h>
#include <cstdint>
#include <cstddef>

#define DEVI __device__ __forceinline__

// ---------------- scratch (device globals; no allocation) ----------------
__device__ float g_V[8192 * 64];                 // stage-1 output
__device__ float g_H[(size_t)8192 * 4096];       // stage-2 output (tf32-rounded)
__device__ float g_Wnr[(size_t)4096 * 4096];     // tf32-rounded Wn

// ---------------- helpers ----------------
DEVI float to_tf32(float x) {
    uint32_t u;
    asm("cvt.rna.tf32.f32 %0, %1;" : "=r"(u) : "f"(x));
    return __uint_as_float(u);
}
DEVI uint32_t smem_u32(const void* p) {
    uint32_t a;
    asm("{ .reg .u64 t; cvta.to.shared.u64 t, %1; cvt.u32.u64 %0, t; }" : "=r"(a) : "l"(p));
    return a;
}
DEVI void cp16(uint32_t saddr, const void* gaddr) {
    asm volatile("cp.async.cg.shared.global [%0], [%1], 16;" :: "r"(saddr), "l"(gaddr) : "memory");
}
DEVI void cp_commit() { asm volatile("cp.async.commit_group;" ::: "memory"); }
DEVI void cp_wait0()  { asm volatile("cp.async.wait_group 0;" ::: "memory"); }
DEVI void cp_wait1()  { asm volatile("cp.async.wait_group 1;" ::: "memory"); }

DEVI void mma8(float c[4], const uint32_t a[4], const uint32_t b[2]) {
    asm("mma.sync.aligned.m16n8k8.row.col.f32.tf32.tf32.f32 "
        "{%0,%1,%2,%3}, {%4,%5,%6,%7}, {%8,%9}, {%0,%1,%2,%3};\n"
        : "+f"(c[0]), "+f"(c[1]), "+f"(c[2]), "+f"(c[3])
        : "r"(a[0]), "r"(a[1]), "r"(a[2]), "r"(a[3]),
          "r"(b[0]), "r"(b[1]));
}

// ============================================================================
// Stage 3: out[8192,4096] = relu( H @ Wn^T + bn )
// mma.sync tf32. 128x256 CTA tile, 64x64 warp tiles (8 warps, 2x4),
// K-tile 32, 2-stage cp.async double buffer. Operands pre-rounded to tf32.
// ============================================================================
static constexpr int S3_LD = 36;                       // padded row stride (floats)
static constexpr int S3_AS = 128 * S3_LD;              // A stage floats
static constexpr int S3_BS = 256 * S3_LD;              // B stage floats
static constexpr int S3_SMEM = 2 * (S3_AS + S3_BS) * (int)sizeof(float);  // 110592 B

DEVI void s3_fill(float* As, float* Bs,
                  const float* __restrict__ A, const float* __restrict__ B,
                  int bm, int bn, int k0, int tid)
{
#pragma unroll
    for (int i = 0; i < 4; ++i) {                       // A: 128 rows x 32 floats = 1024 chunks
        const int ch = tid + (i << 8);
        const int r = ch >> 3, c4 = ch & 7;
        cp16(smem_u32(As + r * S3_LD + c4 * 4),
             A + ((size_t)(bm * 128 + r) << 12) + k0 + (c4 << 2));
    }
#pragma unroll
    for (int i = 0; i < 8; ++i) {                       // B: 256 rows x 32 floats = 2048 chunks
        const int ch = tid + (i << 8);
        const int r = ch >> 3, c4 = ch & 7;
        cp16(smem_u32(Bs + r * S3_LD + c4 * 4),
             B + ((size_t)(bn * 256 + r) << 12) + k0 + (c4 << 2));
    }
}

__global__ void __launch_bounds__(256, 1)
gemm3_mma(const float* __restrict__ A,    // g_H   [8192,4096] tf32-rounded
          const float* __restrict__ B,    // g_Wnr [4096,4096] tf32-rounded
          const float* __restrict__ bias,
          float* __restrict__ C)
{
    constexpr int NK = 128;                             // 4096 / 32
    extern __shared__ float smem[];
    float* const Asb[2] = { smem, smem + S3_AS };
    float* const Bsb[2] = { smem + 2 * S3_AS, smem + 2 * S3_AS + S3_BS };

    const int tid  = threadIdx.x;
    const int lane = tid & 31;
    const int wid  = tid >> 5;
    const int g    = lane >> 2;       // 0..7
    const int tig  = lane & 3;        // 0..3
    const int wm   = (wid >> 2) * 64; // warp m offset (2 warp-rows of 64)
    const int wn   = (wid & 3) * 64;  // warp n offset (4 warp-cols of 64)
    const int bn = blockIdx.x, bm = blockIdx.y;

    float acc[4][8][4];
#pragma unroll
    for (int mt = 0; mt < 4; ++mt)
#pragma unroll
        for (int nt = 0; nt < 8; ++nt)
#pragma unroll
            for (int i = 0; i < 4; ++i) acc[mt][nt][i] = 0.f;

    s3_fill(Asb[0], Bsb[0], A, B, bm, bn, 0,  tid); cp_commit();
    s3_fill(Asb[1], Bsb[1], A, B, bm, bn, 32, tid); cp_commit();

    for (int kt = 0; kt < NK; ++kt) {
        const int s = kt & 1;
        if (kt == NK - 1) cp_wait0(); else cp_wait1();
        __syncthreads();

        const float* __restrict__ Ac = Asb[s];
        const float* __restrict__ Bc = Bsb[s];
#pragma unroll
        for (int ks = 0; ks < 4; ++ks) {
            const int c0 = ks * 8 + tig;
            uint32_t af[4][4];
            uint32_t bf[8][2];
#pragma unroll
            for (int mt = 0; mt < 4; ++mt) {
                const int r0 = wm + mt * 16 + g;
                af[mt][0] = __float_as_uint(Ac[r0 * S3_LD + c0]);
                af[mt][1] = __float_as_uint(Ac[(r0 + 8) * S3_LD + c0]);
                af[mt][2] = __float_as_uint(Ac[r0 * S3_LD + c0 + 4]);
                af[mt][3] = __float_as_uint(Ac[(r0 + 8) * S3_LD + c0 + 4]);
            }
#pragma unroll
            for (int nt = 0; nt < 8; ++nt) {
                const int r0 = wn + nt * 8 + g;
                bf[nt][0] = __float_as_uint(Bc[r0 * S3_LD + c0]);
                bf[nt][1] = __float_as_uint(Bc[r0 * S3_LD + c0 + 4]);
            }
#pragma unroll
            for (int mt = 0; mt < 4; ++mt)
#pragma unroll
                for (int nt = 0; nt < 8; ++nt)
                    mma8(acc[mt][nt], af[mt], bf[nt]);
        }

        __syncthreads();                // all warps done reading stage s
        const int nt2 = kt + 2;
        if (nt2 < NK) {
            s3_fill(Asb[s], Bsb[s], A, B, bm, bn, nt2 * 32, tid);
            cp_commit();
        }
    }

    // epilogue: bias + relu, float2 stores
#pragma unroll
    for (int mt = 0; mt < 4; ++mt) {
#pragma unroll
        for (int nt = 0; nt < 8; ++nt) {
            const int m = bm * 128 + wm + mt * 16 + g;
            const int n = bn * 256 + wn + nt * 8 + 2 * tig;
            const float2 bb = *(const float2*)(bias + n);
            float2 v0, v1;
            v0.x = fmaxf(acc[mt][nt][0] + bb.x, 0.f);
            v0.y = fmaxf(acc[mt][nt][1] + bb.y, 0.f);
            v1.x = fmaxf(acc[mt][nt][2] + bb.x, 0.f);
            v1.y = fmaxf(acc[mt][nt][3] + bb.y, 0.f);
            *(float2*)(C + ((size_t)m << 12) + n)       = v0;
            *(float2*)(C + ((size_t)(m + 8) << 12) + n) = v1;
        }
    }
}

// ============================================================================
// Elementwise tf32 rounding pass (Wn -> g_Wnr)
// ============================================================================
__global__ void round_tf32_kernel(const float4* __restrict__ in, float4* __restrict__ out, int n4)
{
    for (int i = blockIdx.x * blockDim.x + threadIdx.x; i < n4; i += gridDim.x * blockDim.x) {
        float4 v = in[i];
        v.x = to_tf32(v.x); v.y = to_tf32(v.y); v.z = to_tf32(v.z); v.w = to_tf32(v.w);
        out[i] = v;
    }
}

// ============================================================================
// V init: V[m][n] = bv[n]  (8192 x 64)
// ============================================================================
__global__ void init_bias_kernel(float4* __restrict__ V, const float4* __restrict__ bv)
{
    for (int i = blockIdx.x * blockDim.x + threadIdx.x; i < 131072; i += gridDim.x * blockDim.x)
        V[i] = bv[i & 15];
}

// ============================================================================
// Stages 1-2: mma.sync tf32 GEMM (proven R8 kernel + split-K support)
// EPI: 0 = +bias ; 1 = +bias +resid, round to tf32 ; 3 = split-K atomicAdd
// Klen = K covered by this CTA (per z-slice); ldk = full row stride.
// ============================================================================
template <int BM, int BN, int EPI>
__global__ void __launch_bounds__(256, 1)
gemm_tf32_kernel(const float* __restrict__ A,
                 const float* __restrict__ B,
                 const float* __restrict__ bias,
                 const float* __restrict__ resid,
                 float* __restrict__ C,
                 int M, int N, int Klen, int ldk)
{
    constexpr int MT = BM / 32;
    constexpr int NT = BN / 32;
    constexpr int LD = 36;

    extern __shared__ float smemf[];
    float* const As0 = smemf;
    float* const As1 = smemf + BM * LD;
    float* const Bs0 = smemf + 2 * BM * LD;
    float* const Bs1 = smemf + 2 * BM * LD + BN * LD;
    float* const Asb[2] = { As0, As1 };
    float* const Bsb[2] = { Bs0, Bs1 };

    const int tid  = threadIdx.x;
    const int lane = tid & 31;
    const int wid  = tid >> 5;
    const int g    = lane >> 2;
    const int tig  = lane & 3;

    const int wm = (wid >> 2) * (BM / 2);
    const int wn = (wid & 3) * (BN / 4);

    const size_t koff = (size_t)blockIdx.z * Klen;
    const float* Ab = A + (size_t)blockIdx.y * BM * ldk + koff;
    const float* Bb = B + (size_t)blockIdx.x * BN * ldk + koff;

    const int lr = tid >> 3;
    const int lc = (tid & 7) * 4;

    float4 ra[MT], rb[NT];
    float acc[MT][NT][4];
#pragma unroll
    for (int mt = 0; mt < MT; ++mt)
#pragma unroll
        for (int nt = 0; nt < NT; ++nt)
#pragma unroll
            for (int i = 0; i < 4; ++i) acc[mt][nt][i] = 0.f;

    const int ktiles = Klen >> 5;

#pragma unroll
    for (int i = 0; i < MT; ++i)
        ra[i] = *(const float4*)(Ab + (size_t)(lr + 32 * i) * ldk + lc);
#pragma unroll
    for (int i = 0; i < NT; ++i)
        rb[i] = *(const float4*)(Bb + (size_t)(lr + 32 * i) * ldk + lc);
#pragma unroll
    for (int i = 0; i < MT; ++i) {
        float4 t = ra[i];
        t.x = to_tf32(t.x); t.y = to_tf32(t.y); t.z = to_tf32(t.z); t.w = to_tf32(t.w);
        *(float4*)&As0[(lr + 32 * i) * LD + lc] = t;
    }
#pragma unroll
    for (int i = 0; i < NT; ++i) {
        float4 t = rb[i];
        t.x = to_tf32(t.x); t.y = to_tf32(t.y); t.z = to_tf32(t.z); t.w = to_tf32(t.w);
        *(float4*)&Bs0[(lr + 32 * i) * LD + lc] = t;
    }
    __syncthreads();

    for (int kt = 0; kt < ktiles; ++kt) {
        const int cur = kt & 1;
        const bool more = (kt + 1) < ktiles;

        if (more) {
            const int ko = (kt + 1) * 32;
#pragma unroll
            for (int i = 0; i < MT; ++i)
                ra[i] = *(const float4*)(Ab + (size_t)(lr + 32 * i) * ldk + ko + lc);
#pragma unroll
            for (int i = 0; i < NT; ++i)
                rb[i] = *(const float4*)(Bb + (size_t)(lr + 32 * i) * ldk + ko + lc);
        }

        const float* __restrict__ Ac = Asb[cur];
        const float* __restrict__ Bc = Bsb[cur];
#pragma unroll
        for (int ks = 0; ks < 4; ++ks) {
            uint32_t af[MT][4];
            uint32_t bf[NT][2];
            const int c0 = ks * 8 + tig;
#pragma unroll
            for (int mt = 0; mt < MT; ++mt) {
                const int r0 = wm + mt * 16 + g;
                af[mt][0] = __float_as_uint(Ac[r0 * LD + c0]);
                af[mt][1] = __float_as_uint(Ac[(r0 + 8) * LD + c0]);
                af[mt][2] = __float_as_uint(Ac[r0 * LD + c0 + 4]);
                af[mt][3] = __float_as_uint(Ac[(r0 + 8) * LD + c0 + 4]);
            }
#pragma unroll
            for (int nt = 0; nt < NT; ++nt) {
                const int r0 = wn + nt * 8 + g;
                bf[nt][0] = __float_as_uint(Bc[r0 * LD + c0]);
                bf[nt][1] = __float_as_uint(Bc[r0 * LD + c0 + 4]);
            }
#pragma unroll
            for (int mt = 0; mt < MT; ++mt)
#pragma unroll
                for (int nt = 0; nt < NT; ++nt)
                    mma8(acc[mt][nt], af[mt], bf[nt]);
        }

        if (more) {
            float* const An = Asb[cur ^ 1];
            float* const Bn = Bsb[cur ^ 1];
#pragma unroll
            for (int i = 0; i < MT; ++i) {
                float4 t = ra[i];
                t.x = to_tf32(t.x); t.y = to_tf32(t.y); t.z = to_tf32(t.z); t.w = to_tf32(t.w);
                *(float4*)&An[(lr + 32 * i) * LD + lc] = t;
            }
#pragma unroll
            for (int i = 0; i < NT; ++i) {
                float4 t = rb[i];
                t.x = to_tf32(t.x); t.y = to_tf32(t.y); t.z = to_tf32(t.z); t.w = to_tf32(t.w);
                *(float4*)&Bn[(lr + 32 * i) * LD + lc] = t;
            }
        }
        __syncthreads();
    }

    const int m0 = blockIdx.y * BM + wm;
    const int n0 = blockIdx.x * BN + wn;
#pragma unroll
    for (int mt = 0; mt < MT; ++mt) {
#pragma unroll
        for (int nt = 0; nt < NT; ++nt) {
            const int m = m0 + mt * 16 + g;
            const int n = n0 + nt * 8 + 2 * tig;
            if (EPI == 3) {
                atomicAdd(C + (size_t)m * N + n,           acc[mt][nt][0]);
                atomicAdd(C + (size_t)m * N + n + 1,       acc[mt][nt][1]);
                atomicAdd(C + (size_t)(m + 8) * N + n,     acc[mt][nt][2]);
                atomicAdd(C + (size_t)(m + 8) * N + n + 1, acc[mt][nt][3]);
            } else {
                const float2 bb = *(const float2*)(bias + n);
                float v0 = acc[mt][nt][0] + bb.x;
                float v1 = acc[mt][nt][1] + bb.y;
                float v2 = acc[mt][nt][2] + bb.x;
                float v3 = acc[mt][nt][3] + bb.y;
                if (EPI == 1) {
                    const float2 r0 = *(const float2*)(resid + (size_t)m * N + n);
                    const float2 r1 = *(const float2*)(resid + (size_t)(m + 8) * N + n);
                    v0 = to_tf32(v0 + r0.x); v1 = to_tf32(v1 + r0.y);
                    v2 = to_tf32(v2 + r1.x); v3 = to_tf32(v3 + r1.y);
                }
                *(float2*)(C + (size_t)m * N + n)       = make_float2(v0, v1);
                *(float2*)(C + (size_t)(m + 8) * N + n) = make_float2(v2, v3);
            }
        }
    }
}

// ============================================================================
// launch
// Inputs (metadata order): x, Wq, bq, Wk, bk, Wv, bv, Wo, bo, Wn, bn
// Singleton softmax => attended == v; Wq/bq/Wk/bk dead.
// ============================================================================
extern "C" void kernel_launch(void* const* d_in, const int* in_sizes, int n_in,
                              void* d_out, int out_size)
{
    const float* x  = (const float*)d_in[0];
    const float* Wv = (const float*)d_in[5];
    const float* bv = (const float*)d_in[6];
    const float* Wo = (const float*)d_in[7];
    const float* bo = (const float*)d_in[8];
    const float* Wn = (const float*)d_in[9];
    const float* bn = (const float*)d_in[10];
    float* out = (float*)d_out;

    float *V = nullptr, *H = nullptr, *Wnr = nullptr;
    cudaGetSymbolAddress((void**)&V,   g_V);
    cudaGetSymbolAddress((void**)&H,   g_H);
    cudaGetSymbolAddress((void**)&Wnr, g_Wnr);

    constexpr int SM64  = 2 * (64 + 64)   * 36 * (int)sizeof(float);
    constexpr int SM128 = 2 * (128 + 128) * 36 * (int)sizeof(float);

    cudaFuncSetAttribute(gemm_tf32_kernel<64, 64, 3>,
                         cudaFuncAttributeMaxDynamicSharedMemorySize, SM64);
    cudaFuncSetAttribute(gemm_tf32_kernel<128, 128, 1>,
                         cudaFuncAttributeMaxDynamicSharedMemorySize, SM128);
    cudaFuncSetAttribute(gemm3_mma,
                         cudaFuncAttributeMaxDynamicSharedMemorySize, S3_SMEM);

    // Round Wn -> tf32 copy (stage-3 B operand)
    round_tf32_kernel<<<4096, 256>>>((const float4*)Wn, (float4*)Wnr, 4096 * 4096 / 4);

    // Stage 1: V = bv ; V += x @ Wv^T  (split-K x4, atomicAdd)
    init_bias_kernel<<<512, 256>>>((float4*)V, (const float4*)bv);
    gemm_tf32_kernel<64, 64, 3><<<dim3(1, 128, 4), 256, SM64>>>(
        x, Wv, nullptr, nullptr, V, 8192, 64, 1024, 4096);

    // Stage 2: H = round_tf32( V @ Wo^T + bo + x )
    gemm_tf32_kernel<128, 128, 1><<<dim3(32, 64, 1), 256, SM128>>>(
        V, Wo, bo, x, H, 8192, 4096, 64, 64);

    // Stage 3: out = relu(H @ Wn^T + bn)  — 128x256 tiles, cp.async pipeline
    gemm3_mma<<<dim3(16, 64), 256, S3_SMEM>>>(H, Wnr, bn, out);
}